// round 1
// baseline (speedup 1.0000x reference)
#include <cuda_runtime.h>

#define N_NODES 100000
#define N_EDGES 3200000
#define IN_FEAT 256
#define OUT_FEAT 128

// Scratch: CSR row pointer derived from sorted edge_row (no dynamic alloc allowed).
__device__ int g_row_ptr[N_NODES + 1];

// ---------------------------------------------------------------------------
// Kernel 1: femb = feat @ W   (M=100000, K=256, N=128), fp32 register-tiled.
// BM=128, BN=128, BK=16, 256 threads, TM=TN=8.
// ---------------------------------------------------------------------------
__global__ __launch_bounds__(256) void gemm_kernel(
    const float* __restrict__ A,   // [M, 256]
    const float* __restrict__ B,   // [256, 128]
    float* __restrict__ C)         // [M, 128]
{
    __shared__ float As[16][132];  // transposed A tile [k][m], padded (2-way max)
    __shared__ float Bs[16][128];  // B tile [k][n]

    const int tid = threadIdx.x;
    const int tx = tid & 15;       // col group: cols tx*8 .. tx*8+7
    const int ty = tid >> 4;       // row group: rows ty*8 .. ty*8+7
    const int row0 = blockIdx.x * 128;

    float acc[8][8];
#pragma unroll
    for (int i = 0; i < 8; i++)
#pragma unroll
        for (int j = 0; j < 8; j++) acc[i][j] = 0.0f;

    for (int k0 = 0; k0 < IN_FEAT; k0 += 16) {
        // Load A tile: 128 rows x 16 cols = 512 float4, 2 per thread.
#pragma unroll
        for (int i = 0; i < 2; i++) {
            int f = tid + i * 256;
            int r = f >> 2;              // 0..127
            int c = (f & 3) * 4;         // 0,4,8,12
            int gr = row0 + r;
            float4 v = make_float4(0.f, 0.f, 0.f, 0.f);
            if (gr < N_NODES)
                v = *(const float4*)(A + (size_t)gr * IN_FEAT + k0 + c);
            As[c + 0][r] = v.x;
            As[c + 1][r] = v.y;
            As[c + 2][r] = v.z;
            As[c + 3][r] = v.w;
        }
        // Load B tile: 16 rows x 128 cols = 512 float4, 2 per thread.
#pragma unroll
        for (int i = 0; i < 2; i++) {
            int f = tid + i * 256;
            int r = f >> 5;              // 0..15
            int c = (f & 31) * 4;        // 0..124
            float4 v = *(const float4*)(B + (size_t)(k0 + r) * OUT_FEAT + c);
            *(float4*)&Bs[r][c] = v;
        }
        __syncthreads();

#pragma unroll
        for (int k = 0; k < 16; k++) {
            float a[8], b[8];
            *(float4*)&a[0] = *(const float4*)&As[k][ty * 8];
            *(float4*)&a[4] = *(const float4*)&As[k][ty * 8 + 4];
            *(float4*)&b[0] = *(const float4*)&Bs[k][tx * 8];
            *(float4*)&b[4] = *(const float4*)&Bs[k][tx * 8 + 4];
#pragma unroll
            for (int i = 0; i < 8; i++)
#pragma unroll
                for (int j = 0; j < 8; j++)
                    acc[i][j] = fmaf(a[i], b[j], acc[i][j]);
        }
        __syncthreads();
    }

    // Write back 8x8 per thread as float4 pairs.
#pragma unroll
    for (int i = 0; i < 8; i++) {
        int gr = row0 + ty * 8 + i;
        if (gr < N_NODES) {
            float* cp = C + (size_t)gr * OUT_FEAT + tx * 8;
            *(float4*)(cp + 0) = make_float4(acc[i][0], acc[i][1], acc[i][2], acc[i][3]);
            *(float4*)(cp + 4) = make_float4(acc[i][4], acc[i][5], acc[i][6], acc[i][7]);
        }
    }
}

// ---------------------------------------------------------------------------
// Kernel 2: row_ptr[i] = lower_bound(edge_row, i)  (edge_row is sorted asc).
// ---------------------------------------------------------------------------
__global__ void rowptr_kernel(const int* __restrict__ edge_row)
{
    int t = blockIdx.x * blockDim.x + threadIdx.x;
    if (t > N_NODES) return;
    int lo = 0, hi = N_EDGES;
    while (lo < hi) {
        int mid = (lo + hi) >> 1;
        if (__ldg(edge_row + mid) < t) lo = mid + 1;
        else hi = mid;
    }
    g_row_ptr[t] = lo;
}

// ---------------------------------------------------------------------------
// Kernel 3: SpMM. One warp per node; lane l owns columns [4l, 4l+4).
// No atomics: sorted rows -> contiguous edge segment per node.
// ---------------------------------------------------------------------------
__global__ __launch_bounds__(256) void spmm_kernel(
    const int* __restrict__ edge_col,
    const float* __restrict__ edge_val,
    const float* __restrict__ femb,   // [N, 128]
    float* __restrict__ x)            // [N, 128]
{
    int warp = (blockIdx.x * blockDim.x + threadIdx.x) >> 5;
    if (warp >= N_NODES) return;
    int lane = threadIdx.x & 31;

    int s = g_row_ptr[warp];
    int e = g_row_ptr[warp + 1];

    float4 acc = make_float4(0.f, 0.f, 0.f, 0.f);
    int i = s;

    // 4-way unroll for MLP (independent L2 gathers in flight).
    for (; i + 4 <= e; i += 4) {
        int c0 = __ldg(edge_col + i + 0);
        int c1 = __ldg(edge_col + i + 1);
        int c2 = __ldg(edge_col + i + 2);
        int c3 = __ldg(edge_col + i + 3);
        float v0 = __ldg(edge_val + i + 0);
        float v1 = __ldg(edge_val + i + 1);
        float v2 = __ldg(edge_val + i + 2);
        float v3 = __ldg(edge_val + i + 3);
        float4 f0 = *(const float4*)(femb + (size_t)c0 * OUT_FEAT + lane * 4);
        float4 f1 = *(const float4*)(femb + (size_t)c1 * OUT_FEAT + lane * 4);
        float4 f2 = *(const float4*)(femb + (size_t)c2 * OUT_FEAT + lane * 4);
        float4 f3 = *(const float4*)(femb + (size_t)c3 * OUT_FEAT + lane * 4);
        acc.x = fmaf(v0, f0.x, acc.x); acc.y = fmaf(v0, f0.y, acc.y);
        acc.z = fmaf(v0, f0.z, acc.z); acc.w = fmaf(v0, f0.w, acc.w);
        acc.x = fmaf(v1, f1.x, acc.x); acc.y = fmaf(v1, f1.y, acc.y);
        acc.z = fmaf(v1, f1.z, acc.z); acc.w = fmaf(v1, f1.w, acc.w);
        acc.x = fmaf(v2, f2.x, acc.x); acc.y = fmaf(v2, f2.y, acc.y);
        acc.z = fmaf(v2, f2.z, acc.z); acc.w = fmaf(v2, f2.w, acc.w);
        acc.x = fmaf(v3, f3.x, acc.x); acc.y = fmaf(v3, f3.y, acc.y);
        acc.z = fmaf(v3, f3.z, acc.z); acc.w = fmaf(v3, f3.w, acc.w);
    }
    for (; i < e; i++) {
        int c = __ldg(edge_col + i);
        float v = __ldg(edge_val + i);
        float4 f = *(const float4*)(femb + (size_t)c * OUT_FEAT + lane * 4);
        acc.x = fmaf(v, f.x, acc.x); acc.y = fmaf(v, f.y, acc.y);
        acc.z = fmaf(v, f.z, acc.z); acc.w = fmaf(v, f.w, acc.w);
    }

    *(float4*)(x + (size_t)warp * OUT_FEAT + lane * 4) = acc;
}

// ---------------------------------------------------------------------------
// Launch. Inputs (metadata order): feat, edge_row, edge_col, edge_val, weight.
// Output: [femb (N*128) | x (N*128)] float32.
// ---------------------------------------------------------------------------
extern "C" void kernel_launch(void* const* d_in, const int* in_sizes, int n_in,
                              void* d_out, int out_size)
{
    const float* feat     = (const float*)d_in[0];
    const int*   edge_row = (const int*)d_in[1];
    const int*   edge_col = (const int*)d_in[2];
    const float* edge_val = (const float*)d_in[3];
    const float* weight   = (const float*)d_in[4];

    float* femb = (float*)d_out;                            // [N, 128]
    float* x    = (float*)d_out + (size_t)N_NODES * OUT_FEAT; // [N, 128]

    // 1) GEMM
    int gemm_blocks = (N_NODES + 127) / 128;
    gemm_kernel<<<gemm_blocks, 256>>>(feat, weight, femb);

    // 2) row_ptr (independent of GEMM; stream order is fine)
    rowptr_kernel<<<(N_NODES + 1 + 255) / 256, 256>>>(edge_row);

    // 3) SpMM: one warp per node -> 100000 warps / 8 warps per block
    int spmm_blocks = (N_NODES + 7) / 8;   // 256 threads = 8 warps
    spmm_kernel<<<spmm_blocks, 256>>>(edge_col, edge_val, femb, x);
}

// round 2
// speedup vs baseline: 1.6338x; 1.6338x over previous
#include <cuda_runtime.h>
#include <cstdint>

#define N_NODES 100000
#define N_EDGES 3200000
#define IN_FEAT 256
#define OUT_FEAT 128

// Scratch: CSR row pointer derived from sorted edge_row.
__device__ int g_row_ptr[N_NODES + 1];

__device__ __forceinline__ uint32_t f2tf32(float f) {
    uint32_t r;
    asm("cvt.rna.tf32.f32 %0, %1;" : "=r"(r) : "f"(f));
    return r;
}

// ---------------------------------------------------------------------------
// GEMM: femb = feat @ W  (M=100000, K=256, N=128) via tf32 mma.sync m16n8k8.
// Block tile 128x128xBK16, 8 warps in 4(M) x 2(N) grid, warp tile 32x64.
// Smem pitches chosen for conflict-free fragment LDS:
//   A pitch 20 floats  -> bank = (20*g + q) % 32, all-distinct over a warp
//   B pitch 136 floats -> bank = (8*q + g) % 32, all-distinct over a warp
// ---------------------------------------------------------------------------
#define AP 20
#define BP 136

__global__ __launch_bounds__(256) void gemm_tf32_kernel(
    const float* __restrict__ A,   // [M, 256] fp32
    const float* __restrict__ B,   // [256, 128] fp32
    float* __restrict__ C)         // [M, 128] fp32
{
    __shared__ uint32_t As[128 * AP];
    __shared__ uint32_t Bs[16 * BP];

    const int tid  = threadIdx.x;
    const int lane = tid & 31;
    const int wid  = tid >> 5;
    const int wm   = wid & 3;          // 0..3 -> rows [wm*32, wm*32+32)
    const int wn   = wid >> 2;         // 0..1 -> cols [wn*64, wn*64+64)
    const int row0 = blockIdx.x * 128;
    const int g    = lane >> 2;        // 0..7
    const int q    = lane & 3;         // 0..3

    float acc[2][8][4];
#pragma unroll
    for (int mi = 0; mi < 2; mi++)
#pragma unroll
        for (int ni = 0; ni < 8; ni++)
#pragma unroll
            for (int j = 0; j < 4; j++) acc[mi][ni][j] = 0.0f;

    // Global-load indices (2 float4 of A, 2 float4 of B per thread per tile)
    const int fa0 = tid, fa1 = tid + 256;          // over 512 float4 (128x16 A)
    const int ar0 = fa0 >> 2, ac0 = (fa0 & 3) * 4;
    const int ar1 = fa1 >> 2, ac1 = (fa1 & 3) * 4;
    const int br0 = fa0 >> 5, bc0 = (fa0 & 31) * 4; // over 512 float4 (16x128 B)
    const int br1 = fa1 >> 5, bc1 = (fa1 & 31) * 4;

    float4 ra0, ra1, rb0, rb1;

    // --- prefetch tile 0 ---
    {
        const int k0 = 0;
        ra0 = (row0 + ar0 < N_NODES) ? *(const float4*)(A + (size_t)(row0 + ar0) * IN_FEAT + k0 + ac0)
                                     : make_float4(0.f, 0.f, 0.f, 0.f);
        ra1 = (row0 + ar1 < N_NODES) ? *(const float4*)(A + (size_t)(row0 + ar1) * IN_FEAT + k0 + ac1)
                                     : make_float4(0.f, 0.f, 0.f, 0.f);
        rb0 = *(const float4*)(B + (size_t)(k0 + br0) * OUT_FEAT + bc0);
        rb1 = *(const float4*)(B + (size_t)(k0 + br1) * OUT_FEAT + bc1);
    }
    // store tile 0
    As[ar0 * AP + ac0 + 0] = f2tf32(ra0.x); As[ar0 * AP + ac0 + 1] = f2tf32(ra0.y);
    As[ar0 * AP + ac0 + 2] = f2tf32(ra0.z); As[ar0 * AP + ac0 + 3] = f2tf32(ra0.w);
    As[ar1 * AP + ac1 + 0] = f2tf32(ra1.x); As[ar1 * AP + ac1 + 1] = f2tf32(ra1.y);
    As[ar1 * AP + ac1 + 2] = f2tf32(ra1.z); As[ar1 * AP + ac1 + 3] = f2tf32(ra1.w);
    Bs[br0 * BP + bc0 + 0] = f2tf32(rb0.x); Bs[br0 * BP + bc0 + 1] = f2tf32(rb0.y);
    Bs[br0 * BP + bc0 + 2] = f2tf32(rb0.z); Bs[br0 * BP + bc0 + 3] = f2tf32(rb0.w);
    Bs[br1 * BP + bc1 + 0] = f2tf32(rb1.x); Bs[br1 * BP + bc1 + 1] = f2tf32(rb1.y);
    Bs[br1 * BP + bc1 + 2] = f2tf32(rb1.z); Bs[br1 * BP + bc1 + 3] = f2tf32(rb1.w);
    __syncthreads();

    const int NKT = IN_FEAT / 16;  // 16
    for (int kt = 0; kt < NKT; kt++) {
        // prefetch next tile into registers (overlaps with compute below)
        if (kt + 1 < NKT) {
            const int k0 = (kt + 1) * 16;
            ra0 = (row0 + ar0 < N_NODES) ? *(const float4*)(A + (size_t)(row0 + ar0) * IN_FEAT + k0 + ac0)
                                         : make_float4(0.f, 0.f, 0.f, 0.f);
            ra1 = (row0 + ar1 < N_NODES) ? *(const float4*)(A + (size_t)(row0 + ar1) * IN_FEAT + k0 + ac1)
                                         : make_float4(0.f, 0.f, 0.f, 0.f);
            rb0 = *(const float4*)(B + (size_t)(k0 + br0) * OUT_FEAT + bc0);
            rb1 = *(const float4*)(B + (size_t)(k0 + br1) * OUT_FEAT + bc1);
        }

        // compute: two k=8 steps within this BK=16 tile
#pragma unroll
        for (int ks = 0; ks < 16; ks += 8) {
            uint32_t af[2][4];
#pragma unroll
            for (int mi = 0; mi < 2; mi++) {
                int m = wm * 32 + mi * 16 + g;
                af[mi][0] = As[m * AP + ks + q];
                af[mi][1] = As[(m + 8) * AP + ks + q];
                af[mi][2] = As[m * AP + ks + q + 4];
                af[mi][3] = As[(m + 8) * AP + ks + q + 4];
            }
            uint32_t bf[8][2];
#pragma unroll
            for (int ni = 0; ni < 8; ni++) {
                int n = wn * 64 + ni * 8 + g;
                bf[ni][0] = Bs[(ks + q) * BP + n];
                bf[ni][1] = Bs[(ks + q + 4) * BP + n];
            }
#pragma unroll
            for (int mi = 0; mi < 2; mi++)
#pragma unroll
                for (int ni = 0; ni < 8; ni++) {
                    asm volatile(
                        "mma.sync.aligned.m16n8k8.row.col.f32.tf32.tf32.f32 "
                        "{%0,%1,%2,%3}, {%4,%5,%6,%7}, {%8,%9}, {%0,%1,%2,%3};"
                        : "+f"(acc[mi][ni][0]), "+f"(acc[mi][ni][1]),
                          "+f"(acc[mi][ni][2]), "+f"(acc[mi][ni][3])
                        : "r"(af[mi][0]), "r"(af[mi][1]), "r"(af[mi][2]), "r"(af[mi][3]),
                          "r"(bf[ni][0]), "r"(bf[ni][1]));
                }
        }

        if (kt + 1 < NKT) {
            __syncthreads();
            As[ar0 * AP + ac0 + 0] = f2tf32(ra0.x); As[ar0 * AP + ac0 + 1] = f2tf32(ra0.y);
            As[ar0 * AP + ac0 + 2] = f2tf32(ra0.z); As[ar0 * AP + ac0 + 3] = f2tf32(ra0.w);
            As[ar1 * AP + ac1 + 0] = f2tf32(ra1.x); As[ar1 * AP + ac1 + 1] = f2tf32(ra1.y);
            As[ar1 * AP + ac1 + 2] = f2tf32(ra1.z); As[ar1 * AP + ac1 + 3] = f2tf32(ra1.w);
            Bs[br0 * BP + bc0 + 0] = f2tf32(rb0.x); Bs[br0 * BP + bc0 + 1] = f2tf32(rb0.y);
            Bs[br0 * BP + bc0 + 2] = f2tf32(rb0.z); Bs[br0 * BP + bc0 + 3] = f2tf32(rb0.w);
            Bs[br1 * BP + bc1 + 0] = f2tf32(rb1.x); Bs[br1 * BP + bc1 + 1] = f2tf32(rb1.y);
            Bs[br1 * BP + bc1 + 2] = f2tf32(rb1.z); Bs[br1 * BP + bc1 + 3] = f2tf32(rb1.w);
            __syncthreads();
        }
    }

    // Epilogue: warp tile 32x64; acc[mi][ni] is an m16n8 tile.
#pragma unroll
    for (int mi = 0; mi < 2; mi++) {
        int r1 = row0 + wm * 32 + mi * 16 + g;
        int r2 = r1 + 8;
#pragma unroll
        for (int ni = 0; ni < 8; ni++) {
            int col = wn * 64 + ni * 8 + 2 * q;
            if (r1 < N_NODES)
                *(float2*)(C + (size_t)r1 * OUT_FEAT + col) =
                    make_float2(acc[mi][ni][0], acc[mi][ni][1]);
            if (r2 < N_NODES)
                *(float2*)(C + (size_t)r2 * OUT_FEAT + col) =
                    make_float2(acc[mi][ni][2], acc[mi][ni][3]);
        }
    }
}

// ---------------------------------------------------------------------------
// row_ptr[i] = lower_bound(edge_row, i)  (edge_row sorted ascending).
// ---------------------------------------------------------------------------
__global__ void rowptr_kernel(const int* __restrict__ edge_row)
{
    int t = blockIdx.x * blockDim.x + threadIdx.x;
    if (t > N_NODES) return;
    int lo = 0, hi = N_EDGES;
    while (lo < hi) {
        int mid = (lo + hi) >> 1;
        if (__ldg(edge_row + mid) < t) lo = mid + 1;
        else hi = mid;
    }
    g_row_ptr[t] = lo;
}

// ---------------------------------------------------------------------------
// SpMM: one warp per node; lane l owns columns [4l, 4l+4). No atomics.
// ---------------------------------------------------------------------------
__global__ __launch_bounds__(256) void spmm_kernel(
    const int* __restrict__ edge_col,
    const float* __restrict__ edge_val,
    const float* __restrict__ femb,   // [N, 128]
    float* __restrict__ x)            // [N, 128]
{
    int warp = (blockIdx.x * blockDim.x + threadIdx.x) >> 5;
    if (warp >= N_NODES) return;
    int lane = threadIdx.x & 31;

    int s = g_row_ptr[warp];
    int e = g_row_ptr[warp + 1];

    float4 acc = make_float4(0.f, 0.f, 0.f, 0.f);
    int i = s;

    for (; i + 4 <= e; i += 4) {
        int c0 = __ldg(edge_col + i + 0);
        int c1 = __ldg(edge_col + i + 1);
        int c2 = __ldg(edge_col + i + 2);
        int c3 = __ldg(edge_col + i + 3);
        float v0 = __ldg(edge_val + i + 0);
        float v1 = __ldg(edge_val + i + 1);
        float v2 = __ldg(edge_val + i + 2);
        float v3 = __ldg(edge_val + i + 3);
        float4 f0 = *(const float4*)(femb + (size_t)c0 * OUT_FEAT + lane * 4);
        float4 f1 = *(const float4*)(femb + (size_t)c1 * OUT_FEAT + lane * 4);
        float4 f2 = *(const float4*)(femb + (size_t)c2 * OUT_FEAT + lane * 4);
        float4 f3 = *(const float4*)(femb + (size_t)c3 * OUT_FEAT + lane * 4);
        acc.x = fmaf(v0, f0.x, acc.x); acc.y = fmaf(v0, f0.y, acc.y);
        acc.z = fmaf(v0, f0.z, acc.z); acc.w = fmaf(v0, f0.w, acc.w);
        acc.x = fmaf(v1, f1.x, acc.x); acc.y = fmaf(v1, f1.y, acc.y);
        acc.z = fmaf(v1, f1.z, acc.z); acc.w = fmaf(v1, f1.w, acc.w);
        acc.x = fmaf(v2, f2.x, acc.x); acc.y = fmaf(v2, f2.y, acc.y);
        acc.z = fmaf(v2, f2.z, acc.z); acc.w = fmaf(v2, f2.w, acc.w);
        acc.x = fmaf(v3, f3.x, acc.x); acc.y = fmaf(v3, f3.y, acc.y);
        acc.z = fmaf(v3, f3.z, acc.z); acc.w = fmaf(v3, f3.w, acc.w);
    }
    for (; i < e; i++) {
        int c = __ldg(edge_col + i);
        float v = __ldg(edge_val + i);
        float4 f = *(const float4*)(femb + (size_t)c * OUT_FEAT + lane * 4);
        acc.x = fmaf(v, f.x, acc.x); acc.y = fmaf(v, f.y, acc.y);
        acc.z = fmaf(v, f.z, acc.z); acc.w = fmaf(v, f.w, acc.w);
    }

    *(float4*)(x + (size_t)warp * OUT_FEAT + lane * 4) = acc;
}

// ---------------------------------------------------------------------------
// Launch. Inputs: feat, edge_row, edge_col, edge_val, weight.
// Output: [femb (N*128) | x (N*128)] float32.
// ---------------------------------------------------------------------------
extern "C" void kernel_launch(void* const* d_in, const int* in_sizes, int n_in,
                              void* d_out, int out_size)
{
    const float* feat     = (const float*)d_in[0];
    const int*   edge_row = (const int*)d_in[1];
    const int*   edge_col = (const int*)d_in[2];
    const float* edge_val = (const float*)d_in[3];
    const float* weight   = (const float*)d_in[4];

    float* femb = (float*)d_out;                              // [N, 128]
    float* x    = (float*)d_out + (size_t)N_NODES * OUT_FEAT; // [N, 128]

    rowptr_kernel<<<(N_NODES + 1 + 255) / 256, 256>>>(edge_row);

    int gemm_blocks = (N_NODES + 127) / 128;   // 782
    gemm_tf32_kernel<<<gemm_blocks, 256>>>(feat, weight, femb);

    int spmm_blocks = (N_NODES + 7) / 8;       // 8 warps/block
    spmm_kernel<<<spmm_blocks, 256>>>(edge_col, edge_val, femb, x);
}